// round 3
// baseline (speedup 1.0000x reference)
#include <cuda_runtime.h>
#include <math.h>

#define D 128
#define MAXN 100000

// Scratch (allocation-free: static __device__ arrays)
__device__ float g_agg[(size_t)MAXN * D];   // 51.2 MB aggregation buffer (reused per layer)
__device__ float g_h[(size_t)MAXN * D];     // 51.2 MB hidden state h1
__device__ float g_deg[MAXN];               // in-degree (same for both layers)

// ---------------------------------------------------------------------------
// K0: zero agg/deg, copy change -> out[0:ND], zero out[ND:2ND] (jump target)
// ---------------------------------------------------------------------------
__global__ void k_init(const float* __restrict__ change, float* __restrict__ out, int n) {
    int i = blockIdx.x * blockDim.x + threadIdx.x;
    int nd4 = n * (D / 4);
    if (i < nd4) {
        float4 c = ((const float4*)change)[i];
        ((float4*)out)[i] = c;
        ((float4*)out)[(size_t)nd4 + i] = make_float4(0.f, 0.f, 0.f, 0.f);
        ((float4*)g_agg)[i] = make_float4(0.f, 0.f, 0.f, 0.f);
    }
    if (i < n) g_deg[i] = 0.f;
}

// ---------------------------------------------------------------------------
// Relational scatter: one warp per edge.
//   msg = x[src] * rel[etype];  agg[dst] += msg (red.v4);  deg[dst] += 1
// ---------------------------------------------------------------------------
__global__ void k_scatter(const float* __restrict__ x, const float* __restrict__ rel,
                          const int* __restrict__ ei, const int* __restrict__ et,
                          int E, int addDeg) {
    int gw = (blockIdx.x * blockDim.x + threadIdx.x) >> 5;
    int lane = threadIdx.x & 31;
    if (gw >= E) return;
    int src = ei[gw];
    int dst = ei[E + gw];
    int t = et[gw];
    float4 xv = ((const float4*)x)[(size_t)src * (D / 4) + lane];
    float4 rv = ((const float4*)rel)[(size_t)t * (D / 4) + lane];
    float4 m = make_float4(xv.x * rv.x, xv.y * rv.y, xv.z * rv.z, xv.w * rv.w);
    float* p = g_agg + (size_t)dst * D + lane * 4;
    asm volatile("red.global.add.v4.f32 [%0], {%1,%2,%3,%4};"
                 :: "l"(p), "f"(m.x), "f"(m.y), "f"(m.z), "f"(m.w) : "memory");
    if (addDeg && lane == 0) atomicAdd(&g_deg[dst], 1.0f);
}

// ---------------------------------------------------------------------------
// Jump diffusion scatter: one warp per jump edge.
//   outD[jdst] += w[e] * emb[jsrc]
// ---------------------------------------------------------------------------
__global__ void k_jump(const float* __restrict__ emb, const float* __restrict__ w,
                       const int* __restrict__ ej, int EJ, float* __restrict__ outD) {
    int gw = (blockIdx.x * blockDim.x + threadIdx.x) >> 5;
    int lane = threadIdx.x & 31;
    if (gw >= EJ) return;
    int src = ej[gw];
    int dst = ej[EJ + gw];
    float wv = w[gw];
    float4 xv = ((const float4*)emb)[(size_t)src * (D / 4) + lane];
    float4 m = make_float4(wv * xv.x, wv * xv.y, wv * xv.z, wv * xv.w);
    float* p = outD + (size_t)dst * D + lane * 4;
    asm volatile("red.global.add.v4.f32 [%0], {%1,%2,%3,%4};"
                 :: "l"(p), "f"(m.x), "f"(m.y), "f"(m.z), "f"(m.w) : "memory");
}

// ---------------------------------------------------------------------------
// Fused layer GEMM (tf32 mma.sync):
//   out[r] = x[r] + res * tanh( (agg[r]/max(deg,1)) @ W + x[r] @ Wl )
//            (+ jw * jump[r] for layer 2)
// Block: 256 thr (8 warps), 128 rows/block, full N=128 cols.
// smem: [W ; Wl] as tf32, 256 x 128, stride 136 (conflict-free B frags).
// ---------------------------------------------------------------------------
#define SB_STRIDE 136
#define SMEM_BYTES (256 * SB_STRIDE * 4)

__device__ __forceinline__ unsigned f2tf(float f) {
    unsigned u;
    asm("cvt.rna.tf32.f32 %0, %1;" : "=r"(u) : "f"(f));
    return u;
}

__device__ __forceinline__ void mma_tf32(float* c, unsigned a0, unsigned a1,
                                         unsigned a2, unsigned a3,
                                         unsigned b0, unsigned b1) {
    asm("mma.sync.aligned.m16n8k8.row.col.f32.tf32.tf32.f32 "
        "{%0,%1,%2,%3}, {%4,%5,%6,%7}, {%8,%9}, {%0,%1,%2,%3};"
        : "+f"(c[0]), "+f"(c[1]), "+f"(c[2]), "+f"(c[3])
        : "r"(a0), "r"(a1), "r"(a2), "r"(a3), "r"(b0), "r"(b1));
}

__global__ __launch_bounds__(256, 1)
void k_gemm(const float* __restrict__ x, const float* __restrict__ W,
            const float* __restrict__ Wl, const float* __restrict__ resp,
            const float* __restrict__ jwp, const float* __restrict__ jumpbuf,
            float* __restrict__ out, int n, int zeroAgg) {
    extern __shared__ unsigned sB[];  // [256][SB_STRIDE] tf32 bits

    const int tid = threadIdx.x;
    // Stage [W ; Wloop] into smem as tf32
    for (int i = tid; i < 256 * 128; i += 256) {
        int k = i >> 7, c = i & 127;
        float v = (k < 128) ? W[k * 128 + c] : Wl[(k - 128) * 128 + c];
        sB[k * SB_STRIDE + c] = f2tf(v);
    }
    __syncthreads();

    const int warp = tid >> 5, lane = tid & 31;
    const int grp = lane >> 2, tig = lane & 3;
    const int r0 = blockIdx.x * 128 + warp * 16 + grp;
    const int r1 = r0 + 8;
    const bool v0 = r0 < n, v1 = r1 < n;

    float rd0 = 0.f, rd1 = 0.f;
    if (v0) rd0 = 1.0f / fmaxf(g_deg[r0], 1.0f);
    if (v1) rd1 = 1.0f / fmaxf(g_deg[r1], 1.0f);

    float acc[16][4];
#pragma unroll
    for (int nt = 0; nt < 16; nt++)
#pragma unroll
        for (int q = 0; q < 4; q++) acc[nt][q] = 0.f;

    for (int ks = 0; ks < 32; ks++) {
        const int k0 = (ks & 15) * 8 + tig;     // col in 128-wide A source
        const float* Asrc;
        float s0, s1;
        if (ks < 16) { Asrc = (const float*)g_agg; s0 = rd0; s1 = rd1; }
        else         { Asrc = x;                   s0 = 1.f; s1 = 1.f; }
        float f0 = v0 ? Asrc[(size_t)r0 * 128 + k0]     * s0 : 0.f;
        float f1 = v1 ? Asrc[(size_t)r1 * 128 + k0]     * s1 : 0.f;
        float f2 = v0 ? Asrc[(size_t)r0 * 128 + k0 + 4] * s0 : 0.f;
        float f3 = v1 ? Asrc[(size_t)r1 * 128 + k0 + 4] * s1 : 0.f;
        unsigned a0 = f2tf(f0), a1 = f2tf(f1), a2 = f2tf(f2), a3 = f2tf(f3);
        const int kb = ks * 8 + tig;            // row in stacked smem B
        const unsigned* pb0 = sB + kb * SB_STRIDE + grp;
        const unsigned* pb1 = sB + (kb + 4) * SB_STRIDE + grp;
#pragma unroll
        for (int nt = 0; nt < 16; nt++) {
            unsigned b0 = pb0[nt * 8];
            unsigned b1 = pb1[nt * 8];
            mma_tf32(acc[nt], a0, a1, a2, a3, b0, b1);
        }
    }

    const float res = resp[0];
    const float jw = jwp ? jwp[0] : 0.f;
#pragma unroll
    for (int nt = 0; nt < 16; nt++) {
        const int c = nt * 8 + tig * 2;
        if (v0) {
            float2 xv = *(const float2*)(x + (size_t)r0 * 128 + c);
            float o0 = xv.x + res * tanhf(acc[nt][0]);
            float o1 = xv.y + res * tanhf(acc[nt][1]);
            if (jumpbuf) {
                float2 jv = *(const float2*)(jumpbuf + (size_t)r0 * 128 + c);
                o0 += jw * jv.x; o1 += jw * jv.y;
            }
            *(float2*)(out + (size_t)r0 * 128 + c) = make_float2(o0, o1);
        }
        if (v1) {
            float2 xv = *(const float2*)(x + (size_t)r1 * 128 + c);
            float o0 = xv.x + res * tanhf(acc[nt][2]);
            float o1 = xv.y + res * tanhf(acc[nt][3]);
            if (jumpbuf) {
                float2 jv = *(const float2*)(jumpbuf + (size_t)r1 * 128 + c);
                o0 += jw * jv.x; o1 += jw * jv.y;
            }
            *(float2*)(out + (size_t)r1 * 128 + c) = make_float2(o0, o1);
        }
    }

    // Zero this warp's agg rows for layer 2 (row-exclusive: no sync needed)
    if (zeroAgg) {
        float4 z = make_float4(0.f, 0.f, 0.f, 0.f);
        if (v0) {
            float4* p = (float4*)(g_agg + (size_t)r0 * 128 + tig * 32);
#pragma unroll
            for (int q = 0; q < 8; q++) p[q] = z;
        }
        if (v1) {
            float4* p = (float4*)(g_agg + (size_t)r1 * 128 + tig * 32);
#pragma unroll
            for (int q = 0; q < 8; q++) p[q] = z;
        }
    }
}

// ---------------------------------------------------------------------------
// Launch sequence (graph-capturable: kernel launches only)
// ---------------------------------------------------------------------------
extern "C" void kernel_launch(void* const* d_in, const int* in_sizes, int n_in,
                              void* d_out, int out_size) {
    const float* emb    = (const float*)d_in[0];
    const float* change = (const float*)d_in[1];
    const float* W1     = (const float*)d_in[2];
    const float* Wl1    = (const float*)d_in[3];
    const float* rel1   = (const float*)d_in[4];
    const float* W2     = (const float*)d_in[5];
    const float* Wl2    = (const float*)d_in[6];
    const float* rel2   = (const float*)d_in[7];
    const float* res    = (const float*)d_in[8];
    const float* jw     = (const float*)d_in[9];
    const float* ewj    = (const float*)d_in[10];
    const int*   ei     = (const int*)d_in[11];
    const int*   et     = (const int*)d_in[12];
    const int*   ej     = (const int*)d_in[13];

    const int N  = in_sizes[0] / 128;
    const int E  = in_sizes[12];
    const int EJ = in_sizes[10];
    if (N <= 0 || E <= 0 || EJ <= 0) return;

    float* out  = (float*)d_out;
    float* outD = out + (size_t)N * 128;

    float* hptr = nullptr;
    cudaGetSymbolAddress((void**)&hptr, g_h);

    cudaFuncSetAttribute(k_gemm, cudaFuncAttributeMaxDynamicSharedMemorySize, SMEM_BYTES);

    const int nd4 = N * 32;
    k_init<<<(nd4 + 255) / 256, 256>>>(change, out, N);
    // layer-1 scatter (also accumulates deg)
    k_scatter<<<(E + 7) / 8, 256>>>(emb, rel1, ei, et, E, 1);
    // jump diffusion into dchange half (independent of convs)
    k_jump<<<(EJ + 7) / 8, 256>>>(emb, ewj, ej, EJ, outD);
    // layer 1: h1 = emb + res*tanh((agg/deg)@W1 + emb@Wloop1); zero agg for L2
    k_gemm<<<(N + 127) / 128, 256, SMEM_BYTES>>>(emb, W1, Wl1, res,
                                                 nullptr, nullptr, hptr, N, 1);
    // layer-2 scatter (deg reused)
    k_scatter<<<(E + 7) / 8, 256>>>(hptr, rel2, ei, et, E, 0);
    // layer 2 + jump combine: dchange = h1 + res*tanh(...) + jw*jump
    k_gemm<<<(N + 127) / 128, 256, SMEM_BYTES>>>(hptr, W2, Wl2, res,
                                                 jw, outD, outD, N, 0);
}

// round 4
// speedup vs baseline: 1.3734x; 1.3734x over previous
#include <cuda_runtime.h>
#include <math.h>

#define D 128
#define MAXN 100000

// Scratch (allocation-free: static __device__ arrays)
__device__ float g_agg[(size_t)MAXN * D];   // 51.2 MB aggregation buffer (reused per layer)
__device__ float g_h[(size_t)MAXN * D];     // 51.2 MB hidden state h1
__device__ float g_deg[MAXN];               // in-degree (same for both layers)

// ---------------------------------------------------------------------------
// K0: zero agg/deg, copy change -> out[0:ND], zero out[ND:2ND] (jump target)
// ---------------------------------------------------------------------------
__global__ void k_init(const float* __restrict__ change, float* __restrict__ out, int n) {
    int i = blockIdx.x * blockDim.x + threadIdx.x;
    int nd4 = n * (D / 4);
    if (i < nd4) {
        float4 c = ((const float4*)change)[i];
        ((float4*)out)[i] = c;
        ((float4*)out)[(size_t)nd4 + i] = make_float4(0.f, 0.f, 0.f, 0.f);
        ((float4*)g_agg)[i] = make_float4(0.f, 0.f, 0.f, 0.f);
    }
    if (i < n) g_deg[i] = 0.f;
}

// ---------------------------------------------------------------------------
// Relational scatter: one warp per edge.
// ---------------------------------------------------------------------------
__global__ void k_scatter(const float* __restrict__ x, const float* __restrict__ rel,
                          const int* __restrict__ ei, const int* __restrict__ et,
                          int E, int addDeg) {
    int gw = (blockIdx.x * blockDim.x + threadIdx.x) >> 5;
    int lane = threadIdx.x & 31;
    if (gw >= E) return;
    int src = ei[gw];
    int dst = ei[E + gw];
    int t = et[gw];
    float4 xv = ((const float4*)x)[(size_t)src * (D / 4) + lane];
    float4 rv = ((const float4*)rel)[(size_t)t * (D / 4) + lane];
    float4 m = make_float4(xv.x * rv.x, xv.y * rv.y, xv.z * rv.z, xv.w * rv.w);
    float* p = g_agg + (size_t)dst * D + lane * 4;
    asm volatile("red.global.add.v4.f32 [%0], {%1,%2,%3,%4};"
                 :: "l"(p), "f"(m.x), "f"(m.y), "f"(m.z), "f"(m.w) : "memory");
    if (addDeg && lane == 0) atomicAdd(&g_deg[dst], 1.0f);
}

// ---------------------------------------------------------------------------
// Jump diffusion scatter: one warp per jump edge.
// ---------------------------------------------------------------------------
__global__ void k_jump(const float* __restrict__ emb, const float* __restrict__ w,
                       const int* __restrict__ ej, int EJ, float* __restrict__ outD) {
    int gw = (blockIdx.x * blockDim.x + threadIdx.x) >> 5;
    int lane = threadIdx.x & 31;
    if (gw >= EJ) return;
    int src = ej[gw];
    int dst = ej[EJ + gw];
    float wv = w[gw];
    float4 xv = ((const float4*)emb)[(size_t)src * (D / 4) + lane];
    float4 m = make_float4(wv * xv.x, wv * xv.y, wv * xv.z, wv * xv.w);
    float* p = outD + (size_t)dst * D + lane * 4;
    asm volatile("red.global.add.v4.f32 [%0], {%1,%2,%3,%4};"
                 :: "l"(p), "f"(m.x), "f"(m.y), "f"(m.z), "f"(m.w) : "memory");
}

// ---------------------------------------------------------------------------
// Fused layer GEMM (tf32 mma.sync), occupancy-optimized:
//   out[r] = x[r] + res * tanh( (agg[r]/max(deg,1)) @ W + x[r] @ Wl )
//            (+ jw * jump[r] for layer 2)
// Two-pass K loop: stage W (pass 0, A=agg/deg) then Wl (pass 1, A=x) in the
// SAME 69.6KB smem buffer -> 3 CTAs/SM. Warp tile 16x64 (acc=32 regs),
// 8 warps = 4 m-tiles x 2 n-tiles = 64 rows x 128 cols per CTA.
// ---------------------------------------------------------------------------
#define SB_STRIDE 136
#define SMEM_BYTES (128 * SB_STRIDE * 4)

__device__ __forceinline__ unsigned f2tf(float f) {
    unsigned u;
    asm("cvt.rna.tf32.f32 %0, %1;" : "=r"(u) : "f"(f));
    return u;
}

__device__ __forceinline__ void mma_tf32(float* c, unsigned a0, unsigned a1,
                                         unsigned a2, unsigned a3,
                                         unsigned b0, unsigned b1) {
    asm("mma.sync.aligned.m16n8k8.row.col.f32.tf32.tf32.f32 "
        "{%0,%1,%2,%3}, {%4,%5,%6,%7}, {%8,%9}, {%0,%1,%2,%3};"
        : "+f"(c[0]), "+f"(c[1]), "+f"(c[2]), "+f"(c[3])
        : "r"(a0), "r"(a1), "r"(a2), "r"(a3), "r"(b0), "r"(b1));
}

__global__ __launch_bounds__(256, 3)
void k_gemm(const float* __restrict__ x, const float* __restrict__ W,
            const float* __restrict__ Wl, const float* __restrict__ resp,
            const float* __restrict__ jwp, const float* __restrict__ jumpbuf,
            float* __restrict__ out, int n, int zeroAgg) {
    extern __shared__ unsigned sB[];  // [128][SB_STRIDE] tf32 bits

    const int tid = threadIdx.x;
    const int warp = tid >> 5, lane = tid & 31;
    const int grp = lane >> 2, tig = lane & 3;
    const int mw = warp >> 1;        // 0..3  (m tile)
    const int nw = warp & 1;         // 0..1  (n half)
    const int r0 = blockIdx.x * 64 + mw * 16 + grp;
    const int r1 = r0 + 8;
    const bool v0 = r0 < n, v1 = r1 < n;

    float rd0 = 0.f, rd1 = 0.f;
    if (v0) rd0 = 1.0f / fmaxf(g_deg[r0], 1.0f);
    if (v1) rd1 = 1.0f / fmaxf(g_deg[r1], 1.0f);

    float acc[8][4];
#pragma unroll
    for (int nt = 0; nt < 8; nt++)
#pragma unroll
        for (int q = 0; q < 4; q++) acc[nt][q] = 0.f;

#pragma unroll 1
    for (int pass = 0; pass < 2; pass++) {
        // Stage this pass's weight matrix (128x128 f32 -> tf32 smem)
        const float* Wp = pass ? Wl : W;
        if (pass) __syncthreads();   // all warps done reading previous pass
        for (int i = tid; i < 128 * 32; i += 256) {
            int k = i >> 5, c4 = i & 31;
            float4 wv = ((const float4*)Wp)[i];
            unsigned* s = sB + k * SB_STRIDE + c4 * 4;
            s[0] = f2tf(wv.x); s[1] = f2tf(wv.y);
            s[2] = f2tf(wv.z); s[3] = f2tf(wv.w);
        }
        __syncthreads();

        const float* Asrc = pass ? x : (const float*)g_agg;
        const float s0 = pass ? 1.f : rd0;
        const float s1 = pass ? 1.f : rd1;

#pragma unroll
        for (int ks = 0; ks < 16; ks++) {
            const int k0 = ks * 8 + tig;
            float f0 = v0 ? Asrc[(size_t)r0 * 128 + k0]     * s0 : 0.f;
            float f1 = v1 ? Asrc[(size_t)r1 * 128 + k0]     * s1 : 0.f;
            float f2 = v0 ? Asrc[(size_t)r0 * 128 + k0 + 4] * s0 : 0.f;
            float f3 = v1 ? Asrc[(size_t)r1 * 128 + k0 + 4] * s1 : 0.f;
            unsigned a0 = f2tf(f0), a1 = f2tf(f1), a2 = f2tf(f2), a3 = f2tf(f3);
            const int kb = ks * 8 + tig;
            const unsigned* pb0 = sB + kb * SB_STRIDE + nw * 64 + grp;
            const unsigned* pb1 = pb0 + 4 * SB_STRIDE;
#pragma unroll
            for (int nt = 0; nt < 8; nt++) {
                unsigned b0 = pb0[nt * 8];
                unsigned b1 = pb1[nt * 8];
                mma_tf32(acc[nt], a0, a1, a2, a3, b0, b1);
            }
        }
    }

    const float res = resp[0];
    const float jw = jwp ? jwp[0] : 0.f;
#pragma unroll
    for (int nt = 0; nt < 8; nt++) {
        const int c = nw * 64 + nt * 8 + tig * 2;
        if (v0) {
            float2 xv = *(const float2*)(x + (size_t)r0 * 128 + c);
            float o0 = xv.x + res * tanhf(acc[nt][0]);
            float o1 = xv.y + res * tanhf(acc[nt][1]);
            if (jumpbuf) {
                float2 jv = *(const float2*)(jumpbuf + (size_t)r0 * 128 + c);
                o0 += jw * jv.x; o1 += jw * jv.y;
            }
            *(float2*)(out + (size_t)r0 * 128 + c) = make_float2(o0, o1);
        }
        if (v1) {
            float2 xv = *(const float2*)(x + (size_t)r1 * 128 + c);
            float o0 = xv.x + res * tanhf(acc[nt][2]);
            float o1 = xv.y + res * tanhf(acc[nt][3]);
            if (jumpbuf) {
                float2 jv = *(const float2*)(jumpbuf + (size_t)r1 * 128 + c);
                o0 += jw * jv.x; o1 += jw * jv.y;
            }
            *(float2*)(out + (size_t)r1 * 128 + c) = make_float2(o0, o1);
        }
    }

    // Zero this warp's agg region for layer 2 (row x col-half exclusive)
    if (zeroAgg) {
        float4 z = make_float4(0.f, 0.f, 0.f, 0.f);
        if (v0) {
            float4* p = (float4*)(g_agg + (size_t)r0 * 128 + nw * 64 + tig * 16);
#pragma unroll
            for (int q = 0; q < 4; q++) p[q] = z;
        }
        if (v1) {
            float4* p = (float4*)(g_agg + (size_t)r1 * 128 + nw * 64 + tig * 16);
#pragma unroll
            for (int q = 0; q < 4; q++) p[q] = z;
        }
    }
}

// ---------------------------------------------------------------------------
// Launch sequence (graph-capturable: kernel launches only)
// ---------------------------------------------------------------------------
extern "C" void kernel_launch(void* const* d_in, const int* in_sizes, int n_in,
                              void* d_out, int out_size) {
    const float* emb    = (const float*)d_in[0];
    const float* change = (const float*)d_in[1];
    const float* W1     = (const float*)d_in[2];
    const float* Wl1    = (const float*)d_in[3];
    const float* rel1   = (const float*)d_in[4];
    const float* W2     = (const float*)d_in[5];
    const float* Wl2    = (const float*)d_in[6];
    const float* rel2   = (const float*)d_in[7];
    const float* res    = (const float*)d_in[8];
    const float* jw     = (const float*)d_in[9];
    const float* ewj    = (const float*)d_in[10];
    const int*   ei     = (const int*)d_in[11];
    const int*   et     = (const int*)d_in[12];
    const int*   ej     = (const int*)d_in[13];

    const int N  = in_sizes[0] / 128;
    const int E  = in_sizes[12];
    const int EJ = in_sizes[10];
    if (N <= 0 || E <= 0 || EJ <= 0) return;

    float* out  = (float*)d_out;
    float* outD = out + (size_t)N * 128;

    float* hptr = nullptr;
    cudaGetSymbolAddress((void**)&hptr, g_h);

    cudaFuncSetAttribute(k_gemm, cudaFuncAttributeMaxDynamicSharedMemorySize, SMEM_BYTES);

    const int nd4 = N * 32;
    k_init<<<(nd4 + 255) / 256, 256>>>(change, out, N);
    // layer-1 scatter (also accumulates deg)
    k_scatter<<<(E + 7) / 8, 256>>>(emb, rel1, ei, et, E, 1);
    // jump diffusion into dchange half (independent of convs)
    k_jump<<<(EJ + 7) / 8, 256>>>(emb, ewj, ej, EJ, outD);
    // layer 1: h1 = emb + res*tanh((agg/deg)@W1 + emb@Wloop1); zero agg for L2
    k_gemm<<<(N + 63) / 64, 256, SMEM_BYTES>>>(emb, W1, Wl1, res,
                                               nullptr, nullptr, hptr, N, 1);
    // layer-2 scatter (deg reused)
    k_scatter<<<(E + 7) / 8, 256>>>(hptr, rel2, ei, et, E, 0);
    // layer 2 + jump combine: dchange = h1 + res*tanh(...) + jw*jump
    k_gemm<<<(N + 63) / 64, 256, SMEM_BYTES>>>(hptr, W2, Wl2, res,
                                               jw, outD, outD, N, 0);
}